// round 2
// baseline (speedup 1.0000x reference)
#include <cuda_runtime.h>
#include <cuda_bf16.h>

// Sobel magnitude: out = sqrt((gx/4)^2 + (gy/4)^2 + 1e-4)
//                      = 0.25 * sqrt(gx^2 + gy^2 + 16e-4)
//
// x: [64, 1, 512, 512] fp32. Each warp owns a 128-wide column strip
// (32 lanes x float4) and slides vertically over RPW output rows, reusing
// per-row separable terms  px = val(x-1) - val(x+1),  sy = val(x-1)+2val(x)+val(x+1)
// in registers. In-strip horizontal halo via warp shuffle; strip-boundary
// halo via 2 predicated scalar loads per row (L1/L2 hits).

#define SOBEL_W 512
#define SOBEL_H 512
#define SOBEL_B 64
#define RPW 16                 // output rows per warp
#define CSTRIPS 4              // 512 / 128
#define EPS16 0.0016f          // 16 * 1e-4

__device__ __forceinline__ float fsqrt_approx(float x) {
    float r;
    asm("sqrt.approx.f32 %0, %1;" : "=f"(r) : "f"(x));
    return r;
}

// Load one image row (r) for this warp's strip; produce separable row terms.
// Rows outside [0, H) behave as zero padding.
__device__ __forceinline__ void load_row(const float* __restrict__ img, int r,
                                         int x0, int lane,
                                         float4& px, float4& sy) {
    if ((unsigned)r >= (unsigned)SOBEL_H) {
        px = make_float4(0.f, 0.f, 0.f, 0.f);
        sy = make_float4(0.f, 0.f, 0.f, 0.f);
        return;
    }
    const float* row = img + (size_t)r * SOBEL_W;
    float4 v = __ldg(reinterpret_cast<const float4*>(row + x0));

    float left  = __shfl_up_sync(0xffffffffu, v.w, 1);
    float right = __shfl_down_sync(0xffffffffu, v.x, 1);
    if (lane == 0)  left  = (x0 > 0)               ? __ldg(row + x0 - 1) : 0.f;
    if (lane == 31) right = (x0 + 4 < SOBEL_W)     ? __ldg(row + x0 + 4) : 0.f;

    px.x = left - v.y;
    px.y = v.x  - v.z;
    px.z = v.y  - v.w;
    px.w = v.z  - right;

    sy.x = fmaf(2.f, v.x, left + v.y);
    sy.y = fmaf(2.f, v.y, v.x  + v.z);
    sy.z = fmaf(2.f, v.z, v.y  + v.w);
    sy.w = fmaf(2.f, v.w, v.z  + right);
}

__device__ __forceinline__ float sobel_mag(float pxm, float px0, float pxp,
                                           float sym, float syp) {
    float gx = fmaf(2.f, px0, pxm + pxp);   // vertical weights 1,2,1 on px
    float gy = sym - syp;                   // vertical weights 1,0,-1 on sy
    return 0.25f * fsqrt_approx(fmaf(gy, gy, fmaf(gx, gx, EPS16)));
}

__global__ __launch_bounds__(256, 4)
void SobelOperator_88828513616269_kernel(const float* __restrict__ in,
                                         float* __restrict__ out) {
    const int gwarp = (blockIdx.x * 256 + threadIdx.x) >> 5;
    const int lane  = threadIdx.x & 31;

    const int warps_per_img = (SOBEL_H / RPW) * CSTRIPS;    // 32 * 4 = 128
    const int b      = gwarp / warps_per_img;
    const int rem    = gwarp % warps_per_img;
    const int ystrip = rem / CSTRIPS;
    const int cstrip = rem % CSTRIPS;       // adjacent warps -> adjacent columns
    const int y0     = ystrip * RPW;
    const int x0     = cstrip * 128 + (lane << 2);

    const float* img  = in  + (size_t)b * (SOBEL_H * SOBEL_W);
    float*       oimg = out + (size_t)b * (SOBEL_H * SOBEL_W);

    float4 pxm, sym, px0, sy0, pxp, syp;
    load_row(img, y0 - 1, x0, lane, pxm, sym);
    load_row(img, y0,     x0, lane, px0, sy0);

#pragma unroll
    for (int i = 0; i < RPW; i++) {
        const int y = y0 + i;
        load_row(img, y + 1, x0, lane, pxp, syp);

        float4 o;
        o.x = sobel_mag(pxm.x, px0.x, pxp.x, sym.x, syp.x);
        o.y = sobel_mag(pxm.y, px0.y, pxp.y, sym.y, syp.y);
        o.z = sobel_mag(pxm.z, px0.z, pxp.z, sym.z, syp.z);
        o.w = sobel_mag(pxm.w, px0.w, pxp.w, sym.w, syp.w);

        *reinterpret_cast<float4*>(oimg + (size_t)y * SOBEL_W + x0) = o;

        pxm = px0; sym = sy0;
        px0 = pxp; sy0 = syp;
    }
}

extern "C" void kernel_launch(void* const* d_in, const int* in_sizes, int n_in,
                              void* d_out, int out_size) {
    const float* x   = (const float*)d_in[0];
    float*       out = (float*)d_out;

    const int total_warps = SOBEL_B * (SOBEL_H / RPW) * CSTRIPS;  // 8192
    const int threads     = 256;
    const int blocks      = total_warps * 32 / threads;            // 1024

    SobelOperator_88828513616269_kernel<<<blocks, threads>>>(x, out);
}

// round 11
// speedup vs baseline: 1.4125x; 1.4125x over previous
#include <cuda_runtime.h>
#include <cuda_bf16.h>

// Sobel magnitude: out = sqrt((gx/4)^2 + (gy/4)^2 + 1e-4)
//                      = 0.25 * sqrt(gx^2 + gy^2 + 16e-4)
//
// x: [64, 1, 512, 512] fp32. Each warp owns a 128-wide column strip
// (32 lanes x float4), slides vertically over RPW output rows, reusing
// per-row separable terms  px = v(x-1) - v(x+1),  sy = v(x-1)+2v(x)+v(x+1)
// in registers.
//
// R11 == R9/R10 (eighth infra timeout; bundle still unmeasured):
//  A) RPW 16 -> 8: 2x warp parallelism (16384 warps)     -> shows up as occ%
//  B) horizontal halo via direct predicated scalar loads
//     instead of warp shuffles: removes SHFL (26-32 cyc)
//     from the LDG->SHFL->FMA critical path, MLP/row 1->3 -> shows up in stalls
//     (halo scalars hit the same L1 lines as the vector loads)

#define SOBEL_W 512
#define SOBEL_H 512
#define SOBEL_B 64
#define RPW 8                  // output rows per warp
#define CSTRIPS 4              // 512 / 128
#define EPS16 0.0016f          // 16 * 1e-4

__device__ __forceinline__ float fsqrt_approx(float x) {
    float r;
    asm("sqrt.approx.f32 %0, %1;" : "=f"(r) : "f"(x));
    return r;
}

// Load one image row (r) for this thread's 4-pixel span; produce separable
// row terms. Rows outside [0, H) behave as zero padding. All three loads
// (vector + 2 halo scalars) are independent -> issue back-to-back.
__device__ __forceinline__ void load_row(const float* __restrict__ img, int r,
                                         int x0,
                                         float4& px, float4& sy) {
    if ((unsigned)r >= (unsigned)SOBEL_H) {
        px = make_float4(0.f, 0.f, 0.f, 0.f);
        sy = make_float4(0.f, 0.f, 0.f, 0.f);
        return;
    }
    const float* row = img + (size_t)r * SOBEL_W;
    float4 v = __ldg(reinterpret_cast<const float4*>(row + x0));
    float left  = (x0 > 0)           ? __ldg(row + x0 - 1) : 0.f;
    float right = (x0 + 4 < SOBEL_W) ? __ldg(row + x0 + 4) : 0.f;

    px.x = left - v.y;
    px.y = v.x  - v.z;
    px.z = v.y  - v.w;
    px.w = v.z  - right;

    sy.x = fmaf(2.f, v.x, left + v.y);
    sy.y = fmaf(2.f, v.y, v.x  + v.z);
    sy.z = fmaf(2.f, v.z, v.y  + v.w);
    sy.w = fmaf(2.f, v.w, v.z  + right);
}

__device__ __forceinline__ float sobel_mag(float pxm, float px0, float pxp,
                                           float sym, float syp) {
    float gx = fmaf(2.f, px0, pxm + pxp);   // vertical weights 1,2,1 on px
    float gy = sym - syp;                   // vertical weights 1,0,-1 on sy
    return 0.25f * fsqrt_approx(fmaf(gy, gy, fmaf(gx, gx, EPS16)));
}

__global__ __launch_bounds__(256)
void SobelOperator_88828513616269_kernel(const float* __restrict__ in,
                                         float* __restrict__ out) {
    const int gwarp = (blockIdx.x * 256 + threadIdx.x) >> 5;
    const int lane  = threadIdx.x & 31;

    const int warps_per_img = (SOBEL_H / RPW) * CSTRIPS;    // 64 * 4 = 256
    const int b      = gwarp / warps_per_img;
    const int rem    = gwarp % warps_per_img;
    const int ystrip = rem / CSTRIPS;
    const int cstrip = rem % CSTRIPS;       // adjacent warps -> adjacent columns
    const int y0     = ystrip * RPW;
    const int x0     = cstrip * 128 + (lane << 2);

    const float* img  = in  + (size_t)b * (SOBEL_H * SOBEL_W);
    float*       oimg = out + (size_t)b * (SOBEL_H * SOBEL_W);

    float4 pxm, sym, px0, sy0, pxp, syp;
    load_row(img, y0 - 1, x0, pxm, sym);
    load_row(img, y0,     x0, px0, sy0);

#pragma unroll
    for (int i = 0; i < RPW; i++) {
        const int y = y0 + i;
        load_row(img, y + 1, x0, pxp, syp);

        float4 o;
        o.x = sobel_mag(pxm.x, px0.x, pxp.x, sym.x, syp.x);
        o.y = sobel_mag(pxm.y, px0.y, pxp.y, sym.y, syp.y);
        o.z = sobel_mag(pxm.z, px0.z, pxp.z, sym.z, syp.z);
        o.w = sobel_mag(pxm.w, px0.w, pxp.w, sym.w, syp.w);

        *reinterpret_cast<float4*>(oimg + (size_t)y * SOBEL_W + x0) = o;

        pxm = px0; sym = sy0;
        px0 = pxp; sy0 = syp;
    }
}

extern "C" void kernel_launch(void* const* d_in, const int* in_sizes, int n_in,
                              void* d_out, int out_size) {
    const float* x   = (const float*)d_in[0];
    float*       out = (float*)d_out;

    const int total_warps = SOBEL_B * (SOBEL_H / RPW) * CSTRIPS;  // 16384
    const int threads     = 256;
    const int blocks      = total_warps * 32 / threads;            // 2048

    SobelOperator_88828513616269_kernel<<<blocks, threads>>>(x, out);
}

// round 13
// speedup vs baseline: 1.4874x; 1.0530x over previous
#include <cuda_runtime.h>
#include <cuda_bf16.h>

// Sobel magnitude: out = sqrt((gx/4)^2 + (gy/4)^2 + 1e-4)
//                      = 0.25 * sqrt(gx^2 + gy^2 + 16e-4)
//
// x: [64, 1, 512, 512] fp32. Each warp owns a 128-wide column strip
// (32 lanes x float4), slides vertically over RPW output rows.
//
// R13 == R12 (infra timeout; unmeasured): software pipelining, prefetch
// distance 2. Iteration i issues the raw LDGs for row y0+i+2, converts the
// raw row loaded last iteration (y0+i+1) into separable terms, and computes
// output row y0+i. Each LDG gets ~2 iterations of independent work before
// its consumers -> L2-hit latency (~250cyc) hidden; kernel should become
// memory-throughput bound.
// (R11 evidence: regs=32 => ptxas kept loads glued to consumers; occ 78.6%,
//  issue 46%, DRAM 53% -- exposed latency, nothing saturated.)

#define SOBEL_W 512
#define SOBEL_H 512
#define SOBEL_B 64
#define RPW 8                  // output rows per warp
#define CSTRIPS 4              // 512 / 128
#define EPS16 0.0016f          // 16 * 1e-4

__device__ __forceinline__ float fsqrt_approx(float x) {
    float r;
    asm("sqrt.approx.f32 %0, %1;" : "=f"(r) : "f"(x));
    return r;
}

// Issue the raw loads for image row r (vector + 2 halo scalars, all
// independent). Rows outside [0, H) give zeros (zero padding).
__device__ __forceinline__ void load_raw(const float* __restrict__ img, int r,
                                         int x0,
                                         float4& v, float& l, float& rt) {
    if ((unsigned)r >= (unsigned)SOBEL_H) {
        v = make_float4(0.f, 0.f, 0.f, 0.f);
        l = 0.f; rt = 0.f;
        return;
    }
    const float* row = img + (size_t)r * SOBEL_W;
    v  = __ldg(reinterpret_cast<const float4*>(row + x0));
    l  = (x0 > 0)           ? __ldg(row + x0 - 1) : 0.f;
    rt = (x0 + 4 < SOBEL_W) ? __ldg(row + x0 + 4) : 0.f;
}

// Convert a raw row to separable terms: px = v(x-1)-v(x+1), sy = v(x-1)+2v(x)+v(x+1)
__device__ __forceinline__ void make_terms(const float4 v, float l, float rt,
                                           float4& px, float4& sy) {
    px.x = l   - v.y;
    px.y = v.x - v.z;
    px.z = v.y - v.w;
    px.w = v.z - rt;

    sy.x = fmaf(2.f, v.x, l   + v.y);
    sy.y = fmaf(2.f, v.y, v.x + v.z);
    sy.z = fmaf(2.f, v.z, v.y + v.w);
    sy.w = fmaf(2.f, v.w, v.z + rt);
}

__device__ __forceinline__ float sobel_mag(float pxm, float px0, float pxp,
                                           float sym, float syp) {
    float gx = fmaf(2.f, px0, pxm + pxp);   // vertical weights 1,2,1 on px
    float gy = sym - syp;                   // vertical weights 1,0,-1 on sy
    return 0.25f * fsqrt_approx(fmaf(gy, gy, fmaf(gx, gx, EPS16)));
}

__global__ __launch_bounds__(256)
void SobelOperator_88828513616269_kernel(const float* __restrict__ in,
                                         float* __restrict__ out) {
    const int gwarp = (blockIdx.x * 256 + threadIdx.x) >> 5;
    const int lane  = threadIdx.x & 31;

    const int warps_per_img = (SOBEL_H / RPW) * CSTRIPS;    // 64 * 4 = 256
    const int b      = gwarp / warps_per_img;
    const int rem    = gwarp % warps_per_img;
    const int ystrip = rem / CSTRIPS;
    const int cstrip = rem % CSTRIPS;       // adjacent warps -> adjacent columns
    const int y0     = ystrip * RPW;
    const int x0     = cstrip * 128 + (lane << 2);

    const float* img  = in  + (size_t)b * (SOBEL_H * SOBEL_W);
    float*       oimg = out + (size_t)b * (SOBEL_H * SOBEL_W);

    // Pipeline prologue: rows y0-1, y0 converted to terms; row y0+1 raw in flight.
    float4 vA, vB, vF;  float lA, rA, lB, rB, lF, rF;
    load_raw(img, y0 - 1, x0, vA, lA, rA);
    load_raw(img, y0,     x0, vB, lB, rB);
    load_raw(img, y0 + 1, x0, vF, lF, rF);

    float4 pxm, sym, px0, sy0;
    make_terms(vA, lA, rA, pxm, sym);
    make_terms(vB, lB, rB, px0, sy0);

#pragma unroll
    for (int i = 0; i < RPW; i++) {
        const int y = y0 + i;

        // 1) Issue next raw load (row y+2) -- no consumers this iteration.
        float4 vN; float lN, rN;
        if (i < RPW - 1) {
            load_raw(img, y + 2, x0, vN, lN, rN);
        } else {
            vN = make_float4(0.f, 0.f, 0.f, 0.f); lN = 0.f; rN = 0.f;
        }

        // 2) Convert the in-flight raw row (y+1), loaded last iteration.
        float4 pxp, syp;
        make_terms(vF, lF, rF, pxp, syp);

        // 3) Output row y.
        float4 o;
        o.x = sobel_mag(pxm.x, px0.x, pxp.x, sym.x, syp.x);
        o.y = sobel_mag(pxm.y, px0.y, pxp.y, sym.y, syp.y);
        o.z = sobel_mag(pxm.z, px0.z, pxp.z, sym.z, syp.z);
        o.w = sobel_mag(pxm.w, px0.w, pxp.w, sym.w, syp.w);
        *reinterpret_cast<float4*>(oimg + (size_t)y * SOBEL_W + x0) = o;

        // 4) Slide.
        pxm = px0; sym = sy0;
        px0 = pxp; sy0 = syp;
        vF = vN; lF = lN; rF = rN;
    }
}

extern "C" void kernel_launch(void* const* d_in, const int* in_sizes, int n_in,
                              void* d_out, int out_size) {
    const float* x   = (const float*)d_in[0];
    float*       out = (float*)d_out;

    const int total_warps = SOBEL_B * (SOBEL_H / RPW) * CSTRIPS;  // 16384
    const int threads     = 256;
    const int blocks      = total_warps * 32 / threads;            // 2048

    SobelOperator_88828513616269_kernel<<<blocks, threads>>>(x, out);
}